// round 11
// baseline (speedup 1.0000x reference)
#include <cuda_runtime.h>
#include <math.h>

#define NB   4
#define LEN  64
#define DM   128
#define DI   256
#define DS   16
#define DTR  8
#define EPSF 1e-5f
#define TPB  512
#define CLS  8            // blocks per batch = cluster size
#define NBLK (NB*CLS)     // 32
#define HT   11           // 8 own tokens + 3 halo

// ------------------------- device scratch (no allocs) -------------------------
__device__ __align__(16) float g_rA [NB*LEN*DM];   // residual ping
__device__ __align__(16) float g_rB [NB*LEN*DM];   // residual pong
__device__ __align__(16) float g_ucm[NB*DI*LEN];   // u=silu(conv)  [b][c][t]
__device__ __align__(16) float g_zs [NB*DI*LEN];   // silu(z)       [b][c][t]
__device__ __align__(16) float g_dt [NB*DI*LEN];   // softplus dt   [b][c][t]
__device__ __align__(16) float g_ys [NB*LEN*DI];   // y*silu(z)     [b][t][c]
__device__ __align__(16) float g_Bm [NB*LEN*DS];   // [b][t][n]
__device__ __align__(16) float g_Cm [NB*LEN*DS];   // [b][t][n]

__device__ __forceinline__ float siluf(float x){ return x / (1.0f + __expf(-x)); }
__device__ __forceinline__ float geluf(float x){ return 0.5f*x*(1.0f + erff(x*0.70710678118654752f)); }
__device__ __forceinline__ float softplusf(float x){ return x > 20.0f ? x : log1pf(expf(x)); }

#define CLUSTER_SYNC() do { \
    __threadfence(); \
    asm volatile("barrier.cluster.arrive.aligned;" ::: "memory"); \
    asm volatile("barrier.cluster.wait.aligned;"   ::: "memory"); } while(0)

// smem float offsets (union layout; live ranges disjoint, see phase comments)
#define OFF_X   0        // [11][128] staged mha / sy [11][256] for out_proj
#define OFF_H1  1408     // [11][128] MLP hidden
#define OFF_R   2816     // [11][128] residual r
#define OFF_H   4224     // [11][128] hn (normed)
#define OFF_XC  0        // [11][256] xc           (aliases OFF_X; sy/x dead)
#define OFF_U   2816     // [8][256]  u            (aliases OFF_R; r dead after hn)
#define OFF_DT  5632     // [8][8]    dt-rank
// scan phase layout
#define SC_DT   0        // [32][68]
#define SC_U    2176     // [32][68]
#define SC_Z    4352     // [32][68]
#define SC_B    6528     // [64][16]
#define SC_C    7552     // [64][16]
#define SM_FLOATS 8576

__global__ void __launch_bounds__(TPB, 1) __cluster_dims__(CLS, 1, 1)
mamba_fused(
    const float* __restrict__ mha, const unsigned char* __restrict__ mask,
    const float* __restrict__ w1,  const float* __restrict__ b1,
    const float* __restrict__ w2,  const float* __restrict__ b2,
    const float* __restrict__ inw, const float* __restrict__ cw,
    const float* __restrict__ cb,  const float* __restrict__ xpw,
    const float* __restrict__ dtw, const float* __restrict__ dtb,
    const float* __restrict__ alg, const float* __restrict__ dsk,
    const float* __restrict__ ow,  const float* __restrict__ bnw,
    const float* __restrict__ nfw, float* __restrict__ out)
{
    const int b   = blockIdx.x >> 3;     // batch
    const int r   = blockIdx.x & 7;      // rank within cluster
    const int t0  = r * 8;               // first own token
    const int tid = threadIdx.x;
    __shared__ __align__(16) float buf[SM_FLOATS];
    __shared__ float sSum[16];
    __shared__ unsigned sVal[4];

    const int j  = tid & 127;            // out channel for DM-wide GEMMs
    const int g2 = tid >> 7;             // token slot group (0..3)
    const int c8 = tid & 255;            // channel for DI-wide maps
    const int g8 = tid >> 8;             // token half (0/1)

    // ---------------- frontend 0: MLP for 11 tokens -> buf[OFF_R], g_rA own ----------------
    {
        for (int i = tid; i < HT*32; i += TPB){          // 352 float4
            const int tk = i >> 5, q = i & 31, t = t0 - 3 + tk;
            float4 v = make_float4(0,0,0,0);
            if (t >= 0) v = ((const float4*)(mha + ((size_t)(b*4096 + t))*DM))[q];
            ((float4*)(buf + OFF_X))[i] = v;
        }
        __syncthreads();
        float acc[3];
        {   const float4* wr = (const float4*)(w1 + (size_t)j*DM);
            const float bb = b1[j];
            acc[0]=acc[1]=acc[2]=bb;
            #pragma unroll 8
            for (int q = 0; q < 32; q++){
                float4 w = wr[q];
                #pragma unroll
                for (int i = 0; i < 3; i++){
                    const int idx = g2 + 4*i;
                    if (idx < HT){
                        float4 v = ((const float4*)(buf + OFF_X + idx*DM))[q];
                        acc[i] += w.x*v.x + w.y*v.y + w.z*v.z + w.w*v.w;
                    }
                }
            }
        }
        __syncthreads();
        #pragma unroll
        for (int i = 0; i < 3; i++){
            const int idx = g2 + 4*i;
            if (idx < HT) buf[OFF_H1 + idx*DM + j] = geluf(acc[i]);
        }
        __syncthreads();
        {   const float4* wr = (const float4*)(w2 + (size_t)j*DM);
            const float bb = b2[j];
            acc[0]=acc[1]=acc[2]=bb;
            #pragma unroll 8
            for (int q = 0; q < 32; q++){
                float4 w = wr[q];
                #pragma unroll
                for (int i = 0; i < 3; i++){
                    const int idx = g2 + 4*i;
                    if (idx < HT){
                        float4 v = ((const float4*)(buf + OFF_H1 + idx*DM))[q];
                        acc[i] += w.x*v.x + w.y*v.y + w.z*v.z + w.w*v.w;
                    }
                }
            }
        }
        #pragma unroll
        for (int i = 0; i < 3; i++){
            const int idx = g2 + 4*i;
            if (idx < HT){
                const int t = t0 - 3 + idx;
                float rv = (t >= 0) ? acc[i] : 0.0f;
                buf[OFF_R + idx*DM + j] = rv;
                if (idx >= 3) g_rA[(b*LEN + t)*DM + j] = rv;
            }
        }
        __syncthreads();
    }

    // ================================ layers ================================
    for (int L = 0; L < 4; L++){
        // ---------- middle: rmsnorm(bnw[L]) + in_proj + conv + x_proj + dt ----------
        {
            // norm sums: warp w handles token w (w<11)
            {
                const int w = tid >> 5, lane = tid & 31;
                if (w < HT){
                    float v0 = buf[OFF_R + w*DM + lane];
                    float v1 = buf[OFF_R + w*DM + lane + 32];
                    float v2 = buf[OFF_R + w*DM + lane + 64];
                    float v3 = buf[OFF_R + w*DM + lane + 96];
                    float s = v0*v0 + v1*v1 + v2*v2 + v3*v3;
                    #pragma unroll
                    for (int o = 16; o > 0; o >>= 1) s += __shfl_xor_sync(0xffffffffu, s, o);
                    if (lane == 0) sSum[w] = s;
                }
            }
            __syncthreads();
            {
                const float* bw = bnw + L*DM;
                #pragma unroll
                for (int i = 0; i < 3; i++){
                    const int idx = g2 + 4*i;
                    if (idx < HT){
                        float rv = buf[OFF_R + idx*DM + j];
                        buf[OFF_H + idx*DM + j] =
                            rv * rsqrtf(sSum[idx]*(1.0f/DM) + EPSF) * bw[j];
                    }
                }
            }
            __syncthreads();
            // in_proj xc rows (0..255): g8=0 -> tokens 0..5, g8=1 -> 6..10
            const float* Wi = inw + (size_t)L*2*DI*DM;
            {
                const float4* wr = (const float4*)(Wi + (size_t)c8*DM);
                const int s0 = g8 ? 6 : 0;
                float a[6] = {0,0,0,0,0,0};
                #pragma unroll 4
                for (int q = 0; q < 32; q++){
                    float4 w = wr[q];
                    #pragma unroll
                    for (int s = 0; s < 6; s++){
                        if (s0 + s < HT){
                            float4 v = ((const float4*)(buf + OFF_H + (s0+s)*DM))[q];
                            a[s] += w.x*v.x + w.y*v.y + w.z*v.z + w.w*v.w;
                        }
                    }
                }
                #pragma unroll
                for (int s = 0; s < 6; s++)
                    if (s0 + s < HT) buf[OFF_XC + (s0+s)*DI + c8] = a[s];
            }
            // z rows (256..511): own tokens 4*g8..4*g8+3 (hn idx +3)
            {
                const float4* wr = (const float4*)(Wi + (size_t)(DI + c8)*DM);
                float a[4] = {0,0,0,0};
                #pragma unroll 8
                for (int q = 0; q < 32; q++){
                    float4 w = wr[q];
                    #pragma unroll
                    for (int s = 0; s < 4; s++){
                        float4 v = ((const float4*)(buf + OFF_H + (3 + 4*g8 + s)*DM))[q];
                        a[s] += w.x*v.x + w.y*v.y + w.z*v.z + w.w*v.w;
                    }
                }
                *(float4*)(g_zs + (b*DI + c8)*LEN + t0 + 4*g8) =
                    make_float4(siluf(a[0]), siluf(a[1]), siluf(a[2]), siluf(a[3]));
            }
            __syncthreads();
            // conv width-4 + silu: own tokens o = 4*g8..4*g8+3; xc idx window o..o+3
            {
                float4 wv = *(const float4*)(cw + ((size_t)L*DI + c8)*4);
                const float bb = cb[L*DI + c8];
                float xv[7];
                #pragma unroll
                for (int s = 0; s < 7; s++) xv[s] = buf[OFF_XC + (4*g8 + s)*DI + c8];
                float u4[4];
                #pragma unroll
                for (int jj = 0; jj < 4; jj++){
                    float y = bb + wv.x*xv[jj] + wv.y*xv[jj+1] + wv.z*xv[jj+2] + wv.w*xv[jj+3];
                    u4[jj] = siluf(y);
                }
                __syncthreads();     // xc reads done before u overwrites aliased region? (OFF_U aliases OFF_R, not OFF_XC) -- kept for safety
                #pragma unroll
                for (int jj = 0; jj < 4; jj++)
                    buf[OFF_U + (4*g8 + jj)*DI + c8] = u4[jj];
                *(float4*)(g_ucm + (b*DI + c8)*LEN + t0 + 4*g8) =
                    make_float4(u4[0], u4[1], u4[2], u4[3]);
            }
            __syncthreads();
            // x_proj: 8 tokens x 40 outs = 320 tasks
            if (tid < 320){
                const int tk = tid / 40, kk = tid % 40;
                const float* xw = xpw + (size_t)L*(DTR + 2*DS)*DI;
                const float4* wr = (const float4*)(xw + (size_t)kk*DI);
                const float4* uv = (const float4*)(buf + OFF_U + tk*DI);
                float a = 0.0f;
                #pragma unroll 8
                for (int q = 0; q < DI/4; q++){
                    float4 w = wr[q], v = uv[q];
                    a += w.x*v.x + w.y*v.y + w.z*v.z + w.w*v.w;
                }
                const int t = t0 + tk;
                if (kk < DTR)            buf[OFF_DT + tk*DTR + kk] = a;
                else if (kk < DTR + DS)  g_Bm[(b*LEN + t)*DS + (kk - DTR)]      = a;
                else                     g_Cm[(b*LEN + t)*DS + (kk - DTR - DS)] = a;
            }
            __syncthreads();
            // dt_proj + softplus: own tokens 4*g8..4*g8+3
            {
                const float* dw = dtw + (size_t)L*DI*DTR;
                float bb = dtb[L*DI + c8];
                float wreg[DTR];
                #pragma unroll
                for (int q = 0; q < DTR; q++) wreg[q] = dw[c8*DTR + q];
                float d4[4];
                #pragma unroll
                for (int jj = 0; jj < 4; jj++){
                    float a = bb;
                    #pragma unroll
                    for (int q = 0; q < DTR; q++) a += buf[OFF_DT + (4*g8 + jj)*DTR + q] * wreg[q];
                    d4[jj] = softplusf(a);
                }
                *(float4*)(g_dt + (b*DI + c8)*LEN + t0 + 4*g8) =
                    make_float4(d4[0], d4[1], d4[2], d4[3]);
            }
        }
        CLUSTER_SYNC();

        // ---------- scan: this block owns channels c0..c0+31 of batch b ----------
        {
            const int c0 = r*32;
            {   // stage B, C (tid<256) and dt/u/z (all threads)
                if (tid < 256){
                    ((float4*)(buf + SC_B))[tid] = ((const float4*)(g_Bm + b*LEN*DS))[tid];
                    ((float4*)(buf + SC_C))[tid] = ((const float4*)(g_Cm + b*LEN*DS))[tid];
                }
                const int cs = tid >> 4, q = tid & 15;
                *(float4*)(buf + SC_DT + cs*68 + q*4) =
                    ((const float4*)(g_dt  + (b*DI + c0 + cs)*LEN))[q];
                *(float4*)(buf + SC_U  + cs*68 + q*4) =
                    ((const float4*)(g_ucm + (b*DI + c0 + cs)*LEN))[q];
                *(float4*)(buf + SC_Z  + cs*68 + q*4) =
                    ((const float4*)(g_zs  + (b*DI + c0 + cs)*LEN))[q];
            }
            __syncthreads();
            const int cs = tid >> 4, n = tid & 15, c = c0 + cs;
            const float A  = -expf(alg[((size_t)L*DI + c)*DS + n]);
            const float Dv = dsk[L*DI + c];
            const float* pd = buf + SC_DT + cs*68;
            const float* pu = buf + SC_U  + cs*68;
            const float* pz = buf + SC_Z  + cs*68;
            float h = 0.0f;
            for (int tq = 0; tq < 16; tq++){
                const int tb = tq*4;
                float4 dt4 = *(const float4*)(pd + tb);
                float4 u4  = *(const float4*)(pu + tb);
                const float* dta = (const float*)&dt4;
                const float* ua  = (const float*)&u4;
                float dA[4], y[4];
                #pragma unroll
                for (int s = 0; s < 4; s++) dA[s] = __expf(dta[s] * A);
                #pragma unroll
                for (int s = 0; s < 4; s++){
                    h = h*dA[s] + (dta[s]*ua[s]) * buf[SC_B + (tb+s)*DS + n];
                    y[s] = h * buf[SC_C + (tb+s)*DS + n];
                }
                #pragma unroll
                for (int o = 1; o < 16; o <<= 1){
                    #pragma unroll
                    for (int s = 0; s < 4; s++)
                        y[s] += __shfl_xor_sync(0xffffffffu, y[s], o, 16);
                }
                if (n == 0){
                    #pragma unroll
                    for (int s = 0; s < 4; s++)
                        g_ys[(b*LEN + tb + s)*DI + c] = (y[s] + ua[s]*Dv) * pz[tb + s];
                }
            }
            __syncthreads();
        }
        CLUSTER_SYNC();

        // ---------- frontend L+1: out_proj(L) for 11 tokens + residual ----------
        if (L < 3){
            const float* rIn  = (L & 1) ? g_rB : g_rA;
            float*       rOut = (L & 1) ? g_rA : g_rB;
            for (int i = tid; i < HT*64; i += TPB){      // 704 float4 of ys
                const int tk = i >> 6, q = i & 63, t = t0 - 3 + tk;
                float4 v = make_float4(0,0,0,0);
                if (t >= 0) v = ((const float4*)(g_ys + (size_t)(b*LEN + t)*DI))[q];
                ((float4*)(buf + OFF_X))[i] = v;
            }
            __syncthreads();
            const float4* wr = (const float4*)(ow + (size_t)L*DM*DI + (size_t)j*DI);
            float acc[3] = {0,0,0};
            #pragma unroll 8
            for (int q = 0; q < 64; q++){
                float4 w = wr[q];
                #pragma unroll
                for (int i = 0; i < 3; i++){
                    const int idx = g2 + 4*i;
                    if (idx < HT){
                        float4 v = ((const float4*)(buf + OFF_X + idx*DI))[q];
                        acc[i] += w.x*v.x + w.y*v.y + w.z*v.z + w.w*v.w;
                    }
                }
            }
            __syncthreads();    // sy reads done before OFF_R writes (disjoint) - ordering for reuse of OFF_X next iter
            #pragma unroll
            for (int i = 0; i < 3; i++){
                const int idx = g2 + 4*i;
                if (idx < HT){
                    const int t = t0 - 3 + idx;
                    float rv = 0.0f;
                    if (t >= 0){
                        rv = acc[i] + rIn[(b*LEN + t)*DM + j];
                        if (idx >= 3) rOut[(b*LEN + t)*DM + j] = rv;
                    }
                    buf[OFF_R + idx*DM + j] = rv;
                }
            }
            __syncthreads();
        }
    }

    // ---------------- final: out_proj(L3) token 63 + rmsnorm + mask ----------------
    if (r == 7){
        // stage ys[t=63][256]
        if (tid < 64)
            ((float4*)buf)[tid] = ((const float4*)(g_ys + (size_t)(b*LEN + 63)*DI))[tid];
        __syncthreads();
        float rv = 0.0f;
        if (tid < 128){
            const float4* wr = (const float4*)(ow + (size_t)3*DM*DI + (size_t)tid*DI);
            float a = 0.0f;
            #pragma unroll 8
            for (int q = 0; q < 64; q++){
                float4 w = wr[q], v = ((const float4*)buf)[q];
                a += w.x*v.x + w.y*v.y + w.z*v.z + w.w*v.w;
            }
            rv = a + g_rB[(b*LEN + 63)*DM + tid];
            float s = rv*rv;
            #pragma unroll
            for (int o = 16; o > 0; o >>= 1) s += __shfl_xor_sync(0xffffffffu, s, o);
            if ((tid & 31) == 0) sSum[tid >> 5] = s;
        }
        // key_valid: any nonzero byte in mask row (b, n=0, 0..63)
        {
            unsigned v = 0;
            if (tid < 64) v = (mask[b*4096 + tid] != 0) ? 1u : 0u;
            unsigned bal = __ballot_sync(0xffffffffu, v != 0u);
            if (tid < 64 && (tid & 31) == 0) sVal[tid >> 5] = bal;
        }
        __syncthreads();
        if (tid < 128){
            const int valid = ((sVal[0] | sVal[1]) != 0u) ? 1 : 0;
            float s = sSum[0] + sSum[1] + sSum[2] + sSum[3];
            float o = rv * rsqrtf(s*(1.0f/DM) + EPSF) * nfw[tid];
            out[b*DM + tid] = valid ? o : 0.0f;
        }
    }
}

// --------------------------------- launch ---------------------------------
extern "C" void kernel_launch(void* const* d_in, const int* in_sizes, int n_in,
                              void* d_out, int out_size)
{
    const float* mha = (const float*)d_in[0];
    const unsigned char* mask = (const unsigned char*)d_in[1];
    const float* w1  = (const float*)d_in[2];
    const float* b1  = (const float*)d_in[3];
    const float* w2  = (const float*)d_in[4];
    const float* b2  = (const float*)d_in[5];
    const float* inw = (const float*)d_in[6];
    const float* cw  = (const float*)d_in[7];
    const float* cb  = (const float*)d_in[8];
    const float* xpw = (const float*)d_in[9];
    const float* dtw = (const float*)d_in[10];
    const float* dtb = (const float*)d_in[11];
    const float* alg = (const float*)d_in[12];
    const float* dsk = (const float*)d_in[13];
    const float* ow  = (const float*)d_in[14];
    const float* bnw = (const float*)d_in[15];
    const float* nfw = (const float*)d_in[16];
    float* out = (float*)d_out;

    mamba_fused<<<NBLK, TPB>>>(mha, mask, w1, b1, w2, b2, inw, cw, cb,
                               xpw, dtw, dtb, alg, dsk, ow, bnw, nfw, out);
}

// round 12
// speedup vs baseline: 1.6462x; 1.6462x over previous
#include <cuda_runtime.h>
#include <math.h>

#define NB   4
#define LEN  64
#define DM   128
#define DI   256
#define DS   16
#define DTR  8
#define EPSF 1e-5f
#define NBLK 64
#define NTHR 128
#define BPB  16          // blocks per batch
#define HT   7           // 3 halo + 4 own tokens

// ------------------------- device scratch (no allocs) -------------------------
__device__ __align__(16) float g_rA [NB*LEN*DM];   // residual ping
__device__ __align__(16) float g_rB [NB*LEN*DM];   // residual pong
__device__ __align__(16) float g_ucm[NB*DI*LEN];   // u=silu(conv)  [b][c][t]
__device__ __align__(16) float g_zs [NB*DI*LEN];   // silu(z)       [b][c][t]
__device__ __align__(16) float g_dt [NB*DI*LEN];   // softplus dt   [b][c][t]
__device__ __align__(16) float g_ys [NB*LEN*DI];   // y*silu(z)     [b][t][c]
__device__ __align__(16) float g_Bm [NB*LEN*DS];   // [b][t][n]
__device__ __align__(16) float g_Cm [NB*LEN*DS];   // [b][t][n]

// per-batch barrier state, padded 128B apart to avoid false sharing
__device__ unsigned g_cnt[NB*32];
__device__ unsigned g_gen[NB*32];

__device__ __forceinline__ float siluf(float x){ return x / (1.0f + __expf(-x)); }
__device__ __forceinline__ float geluf(float x){ return 0.5f*x*(1.0f + erff(x*0.70710678118654752f)); }
__device__ __forceinline__ float softplusf(float x){ return x > 20.0f ? x : log1pf(expf(x)); }

__device__ __forceinline__ void st_rel(unsigned* p, unsigned v){
    asm volatile("st.global.release.gpu.u32 [%0], %1;" :: "l"(p), "r"(v) : "memory");
}
__device__ __forceinline__ unsigned ld_acq(unsigned* p){
    unsigned v;
    asm volatile("ld.global.acquire.gpu.u32 %0, [%1];" : "=r"(v) : "l"(p) : "memory");
    return v;
}

// per-batch monotonic-epoch barrier: 16 arrivals
__device__ __forceinline__ void gbar(int b, unsigned k)
{
    __syncthreads();
    if (threadIdx.x == 0){
        __threadfence();
        unsigned prev = atomicAdd(&g_cnt[b*32], 1u);
        if (prev == k*BPB - 1u){
            st_rel(&g_gen[b*32], k);
        } else {
            while ((int)(ld_acq(&g_gen[b*32]) - k) < 0) {}
        }
    }
    __syncthreads();
}

// smem float offsets (disjoint regions, 6432 floats = 25.7 KB)
#define OFF_STG 0        // [7][256] ys stage; for L0: mha [7][128] at 0 + h1 at 896
#define OFF_H1  896
#define OFF_R   1792     // [7][128]
#define OFF_HN  2688     // [7][128]
#define OFF_XC  3584     // [7][256]
#define OFF_U   5376     // [4][256]
#define OFF_DT  6400     // [4][8]
// scan layout (aliases everything; separated by barrier + syncthreads)
#define SC_DT   0        // [16][72]
#define SC_U    1152
#define SC_Z    2304
#define SC_B    3456     // [64][16]
#define SC_C    4480
#define SMSZ    6432

__global__ void __launch_bounds__(NTHR) mamba_fused(
    const float* __restrict__ mha, const unsigned char* __restrict__ mask,
    const float* __restrict__ w1,  const float* __restrict__ b1,
    const float* __restrict__ w2,  const float* __restrict__ b2,
    const float* __restrict__ inw, const float* __restrict__ cw,
    const float* __restrict__ cb,  const float* __restrict__ xpw,
    const float* __restrict__ dtw, const float* __restrict__ dtb,
    const float* __restrict__ alg, const float* __restrict__ dsk,
    const float* __restrict__ ow,  const float* __restrict__ bnw,
    const float* __restrict__ nfw, float* __restrict__ out)
{
    const int blk = blockIdx.x, tid = threadIdx.x;
    const int b   = blk >> 4;          // batch
    const int tg  = blk & 15;          // token group
    const int t0  = tg * 4;            // first own token
    const int j   = tid;               // 0..127
    __shared__ __align__(16) float buf[SMSZ];
    __shared__ float sSum[8];
    __shared__ unsigned sVal[2];
    unsigned k = ld_acq(&g_gen[b*32]);     // stable epoch base

    // ================================ layers ================================
    for (int L = 0; L < 4; L++){
        // ---------- fused: (MLP | out_proj+res) + rmsnorm + in_proj + conv + x_proj + dt ----------
        float rr[HT];
        if (L == 0){
            // stage mha 7 tokens [7][128]
            for (int i = tid; i < HT*32; i += NTHR){
                const int tk = i >> 5, q = i & 31, t = t0 - 3 + tk;
                float4 v = make_float4(0,0,0,0);
                if (t >= 0) v = ((const float4*)(mha + ((size_t)(b*4096 + t))*DM))[q];
                ((float4*)(buf + OFF_STG))[i] = v;
            }
            __syncthreads();
            float acc[HT];
            {   const float bb = b1[j];
                #pragma unroll
                for (int s = 0; s < HT; s++) acc[s] = bb;
                const float4* wr = (const float4*)(w1 + (size_t)j*DM);
                #pragma unroll 4
                for (int q = 0; q < 32; q++){
                    float4 w = wr[q];
                    #pragma unroll
                    for (int s = 0; s < HT; s++){
                        float4 v = ((const float4*)(buf + OFF_STG + s*DM))[q];
                        acc[s] += w.x*v.x + w.y*v.y + w.z*v.z + w.w*v.w;
                    }
                }
            }
            __syncthreads();
            #pragma unroll
            for (int s = 0; s < HT; s++) buf[OFF_H1 + s*DM + j] = geluf(acc[s]);
            __syncthreads();
            {   const float bb = b2[j];
                #pragma unroll
                for (int s = 0; s < HT; s++) acc[s] = bb;
                const float4* wr = (const float4*)(w2 + (size_t)j*DM);
                #pragma unroll 4
                for (int q = 0; q < 32; q++){
                    float4 w = wr[q];
                    #pragma unroll
                    for (int s = 0; s < HT; s++){
                        float4 v = ((const float4*)(buf + OFF_H1 + s*DM))[q];
                        acc[s] += w.x*v.x + w.y*v.y + w.z*v.z + w.w*v.w;
                    }
                }
            }
            #pragma unroll
            for (int s = 0; s < HT; s++){
                const int t = t0 - 3 + s;
                rr[s] = (t >= 0) ? acc[s] : 0.0f;
            }
        } else {
            // stage ys 7 tokens [7][256]
            for (int i = tid; i < HT*64; i += NTHR){
                const int tk = i >> 6, q = i & 63, t = t0 - 3 + tk;
                float4 v = make_float4(0,0,0,0);
                if (t >= 0) v = __ldcg((const float4*)(g_ys + (size_t)(b*LEN + t)*DI) + q);
                ((float4*)(buf + OFF_STG))[i] = v;
            }
            __syncthreads();
            const float* rIn = (L & 1) ? g_rA : g_rB;
            float acc[HT];
            #pragma unroll
            for (int s = 0; s < HT; s++) acc[s] = 0.0f;
            const float4* wr = (const float4*)(ow + (size_t)(L-1)*DM*DI + (size_t)j*DI);
            #pragma unroll 4
            for (int q = 0; q < 64; q++){
                float4 w = wr[q];
                #pragma unroll
                for (int s = 0; s < HT; s++){
                    float4 v = ((const float4*)(buf + OFF_STG + s*DI))[q];
                    acc[s] += w.x*v.x + w.y*v.y + w.z*v.z + w.w*v.w;
                }
            }
            #pragma unroll
            for (int s = 0; s < HT; s++){
                const int t = t0 - 3 + s;
                rr[s] = (t >= 0) ? (acc[s] + __ldcg(rIn + (b*LEN + t)*DM + j)) : 0.0f;
            }
        }
        // r -> smem; own 4 tokens -> residual-out global
        {
            float* rOut = (L & 1) ? g_rB : g_rA;
            #pragma unroll
            for (int s = 0; s < HT; s++) buf[OFF_R + s*DM + j] = rr[s];
            #pragma unroll
            for (int s = 3; s < HT; s++)
                rOut[(b*LEN + t0 + s - 3)*DM + j] = rr[s];
        }
        __syncthreads();
        // rmsnorm sums: warp w -> tokens w, w+4
        {
            const int w = tid >> 5, lane = tid & 31;
            #pragma unroll
            for (int rep = 0; rep < 2; rep++){
                const int tok = w + 4*rep;
                if (tok < HT){
                    float v0 = buf[OFF_R + tok*DM + lane];
                    float v1 = buf[OFF_R + tok*DM + lane + 32];
                    float v2 = buf[OFF_R + tok*DM + lane + 64];
                    float v3 = buf[OFF_R + tok*DM + lane + 96];
                    float s = v0*v0 + v1*v1 + v2*v2 + v3*v3;
                    #pragma unroll
                    for (int o = 16; o > 0; o >>= 1) s += __shfl_xor_sync(0xffffffffu, s, o);
                    if (lane == 0) sSum[tok] = s;
                }
            }
        }
        __syncthreads();
        {
            const float* bw = bnw + L*DM;
            const float bwj = bw[j];
            #pragma unroll
            for (int s = 0; s < HT; s++)
                buf[OFF_HN + s*DM + j] = rr[s] * rsqrtf(sSum[s]*(1.0f/DM) + EPSF) * bwj;
        }
        __syncthreads();
        // in_proj: xc rows (2 per thread) x 7 tokens -> smem
        const float* Wi = inw + (size_t)L*2*DI*DM;
        #pragma unroll
        for (int rr2 = 0; rr2 < 2; rr2++){
            const int c = j + rr2*128;
            const float4* wr = (const float4*)(Wi + (size_t)c*DM);
            float a[HT];
            #pragma unroll
            for (int s = 0; s < HT; s++) a[s] = 0.0f;
            #pragma unroll 4
            for (int q = 0; q < 32; q++){
                float4 w = wr[q];
                #pragma unroll
                for (int s = 0; s < HT; s++){
                    float4 v = ((const float4*)(buf + OFF_HN + s*DM))[q];
                    a[s] += w.x*v.x + w.y*v.y + w.z*v.z + w.w*v.w;
                }
            }
            #pragma unroll
            for (int s = 0; s < HT; s++) buf[OFF_XC + s*DI + c] = a[s];
        }
        // z rows (2 per thread) x own 4 tokens -> g_zs
        #pragma unroll
        for (int rr2 = 0; rr2 < 2; rr2++){
            const int c = j + rr2*128;
            const float4* wr = (const float4*)(Wi + (size_t)(DI + c)*DM);
            float a[4] = {0,0,0,0};
            #pragma unroll 8
            for (int q = 0; q < 32; q++){
                float4 w = wr[q];
                #pragma unroll
                for (int s = 0; s < 4; s++){
                    float4 v = ((const float4*)(buf + OFF_HN + (3 + s)*DM))[q];
                    a[s] += w.x*v.x + w.y*v.y + w.z*v.z + w.w*v.w;
                }
            }
            *(float4*)(g_zs + (b*DI + c)*LEN + t0) =
                make_float4(siluf(a[0]), siluf(a[1]), siluf(a[2]), siluf(a[3]));
        }
        __syncthreads();
        // conv width-4 + silu: 2 channels per thread
        #pragma unroll
        for (int rr2 = 0; rr2 < 2; rr2++){
            const int c = j + rr2*128;
            float4 wv = *(const float4*)(cw + ((size_t)L*DI + c)*4);
            const float bb = cb[L*DI + c];
            float xv[HT];
            #pragma unroll
            for (int s = 0; s < HT; s++) xv[s] = buf[OFF_XC + s*DI + c];
            float u4[4];
            #pragma unroll
            for (int jj = 0; jj < 4; jj++){
                float y = bb + wv.x*xv[jj] + wv.y*xv[jj+1] + wv.z*xv[jj+2] + wv.w*xv[jj+3];
                u4[jj] = siluf(y);
                buf[OFF_U + jj*DI + c] = u4[jj];
            }
            *(float4*)(g_ucm + (b*DI + c)*LEN + t0) =
                make_float4(u4[0], u4[1], u4[2], u4[3]);
        }
        __syncthreads();
        // x_proj: 4 tokens x 40 outs = 160 tasks
        #pragma unroll
        for (int rep = 0; rep < 2; rep++){
            const int task = tid + rep*128;
            if (task < 160){
                const int kk = task % 40, tk = task / 40;
                const float* xw = xpw + (size_t)L*(DTR + 2*DS)*DI;
                const float4* wr = (const float4*)(xw + (size_t)kk*DI);
                const float4* uv = (const float4*)(buf + OFF_U + tk*DI);
                float a = 0.0f;
                #pragma unroll 8
                for (int q = 0; q < DI/4; q++){
                    float4 w = wr[q], v = uv[q];
                    a += w.x*v.x + w.y*v.y + w.z*v.z + w.w*v.w;
                }
                const int t = t0 + tk;
                if (kk < DTR)            buf[OFF_DT + tk*DTR + kk] = a;
                else if (kk < DTR + DS)  g_Bm[(b*LEN + t)*DS + (kk - DTR)]      = a;
                else                     g_Cm[(b*LEN + t)*DS + (kk - DTR - DS)] = a;
            }
        }
        __syncthreads();
        // dt_proj + softplus: 2 channels per thread
        #pragma unroll
        for (int rr2 = 0; rr2 < 2; rr2++){
            const int c = j + rr2*128;
            const float* dw = dtw + (size_t)L*DI*DTR;
            float bb = dtb[L*DI + c];
            float wreg[DTR];
            #pragma unroll
            for (int q = 0; q < DTR; q++) wreg[q] = dw[c*DTR + q];
            float d4[4];
            #pragma unroll
            for (int tk = 0; tk < 4; tk++){
                float a = bb;
                #pragma unroll
                for (int q = 0; q < DTR; q++) a += buf[OFF_DT + tk*DTR + q] * wreg[q];
                d4[tk] = softplusf(a);
            }
            *(float4*)(g_dt + (b*DI + c)*LEN + t0) =
                make_float4(d4[0], d4[1], d4[2], d4[3]);
        }
        gbar(b, ++k);

        // ---------- scan: block=(b, 16-ch slice); thread=(cs, n2) 2 states ----------
        {
            const int c0 = tg*16;
            for (int it = tid; it < 256; it += NTHR){
                const int cs = it >> 4, q = it & 15;
                *(float4*)(buf + SC_DT + cs*72 + q*4) =
                    __ldcg((const float4*)(g_dt  + (b*DI + c0 + cs)*LEN) + q);
                *(float4*)(buf + SC_U  + cs*72 + q*4) =
                    __ldcg((const float4*)(g_ucm + (b*DI + c0 + cs)*LEN) + q);
                *(float4*)(buf + SC_Z  + cs*72 + q*4) =
                    __ldcg((const float4*)(g_zs  + (b*DI + c0 + cs)*LEN) + q);
            }
            for (int q = tid; q < 256; q += NTHR){
                ((float4*)(buf + SC_B))[q] = __ldcg((const float4*)(g_Bm + b*LEN*DS) + q);
                ((float4*)(buf + SC_C))[q] = __ldcg((const float4*)(g_Cm + b*LEN*DS) + q);
            }
            __syncthreads();
            const int cs = tid >> 3, n2 = tid & 7, c = c0 + cs;
            const float* ap = alg + ((size_t)L*DI + c)*DS + 2*n2;
            const float A0 = -expf(ap[0]);
            const float A1 = -expf(ap[1]);
            const float Dv = dsk[L*DI + c];
            const float* pd = buf + SC_DT + cs*72;
            const float* pu = buf + SC_U  + cs*72;
            const float* pz = buf + SC_Z  + cs*72;
            float h0 = 0.0f, h1 = 0.0f;
            for (int tq = 0; tq < 16; tq++){
                const int tb = tq*4;
                float4 dt4 = *(const float4*)(pd + tb);
                float4 u4  = *(const float4*)(pu + tb);
                const float* dta = (const float*)&dt4;
                const float* ua  = (const float*)&u4;
                float y[4];
                #pragma unroll
                for (int s = 0; s < 4; s++){
                    const float dtv = dta[s];
                    const float dtu = dtv * ua[s];
                    float2 Bv = *(const float2*)(buf + SC_B + (tb+s)*DS + 2*n2);
                    float2 Cv = *(const float2*)(buf + SC_C + (tb+s)*DS + 2*n2);
                    h0 = h0*__expf(dtv*A0) + dtu*Bv.x;
                    h1 = h1*__expf(dtv*A1) + dtu*Bv.y;
                    y[s] = h0*Cv.x + h1*Cv.y;
                }
                #pragma unroll
                for (int o = 1; o < 8; o <<= 1){
                    #pragma unroll
                    for (int s = 0; s < 4; s++)
                        y[s] += __shfl_xor_sync(0xffffffffu, y[s], o, 8);
                }
                if (n2 == 0){
                    #pragma unroll
                    for (int s = 0; s < 4; s++)
                        g_ys[(b*LEN + tb + s)*DI + c] = (y[s] + ua[s]*Dv) * pz[tb + s];
                }
            }
            __syncthreads();
        }
        gbar(b, ++k);
    }

    // ---------------- final: out_proj(L3) t=63 + residual + rmsnorm + mask ----------------
    if (tg == 15){
        if (tid < 64)
            ((float4*)buf)[tid] = __ldcg((const float4*)(g_ys + (size_t)(b*LEN + 63)*DI) + tid);
        __syncthreads();
        const float4* wr = (const float4*)(ow + (size_t)3*DM*DI + (size_t)j*DI);
        float a = 0.0f;
        #pragma unroll 8
        for (int q = 0; q < 64; q++){
            float4 w = wr[q], v = ((const float4*)buf)[q];
            a += w.x*v.x + w.y*v.y + w.z*v.z + w.w*v.w;
        }
        float rv = a + g_rB[(b*LEN + 63)*DM + j];    // own write at L3
        float s = rv*rv;
        #pragma unroll
        for (int o = 16; o > 0; o >>= 1) s += __shfl_xor_sync(0xffffffffu, s, o);
        if ((tid & 31) == 0) sSum[tid >> 5] = s;
        // key_valid: any nonzero byte in mask row (b, n=0, 0..63)
        {
            unsigned v = 0;
            if (tid < 64) v = (mask[b*4096 + tid] != 0) ? 1u : 0u;
            unsigned bal = __ballot_sync(0xffffffffu, v != 0u);
            if (tid < 64 && (tid & 31) == 0) sVal[tid >> 5] = bal;
        }
        __syncthreads();
        const int valid = ((sVal[0] | sVal[1]) != 0u) ? 1 : 0;
        s = sSum[0] + sSum[1] + sSum[2] + sSum[3];
        float o = rv * rsqrtf(s*(1.0f/DM) + EPSF) * nfw[j];
        out[b*DM + j] = valid ? o : 0.0f;
    }
}

// --------------------------------- launch ---------------------------------
extern "C" void kernel_launch(void* const* d_in, const int* in_sizes, int n_in,
                              void* d_out, int out_size)
{
    const float* mha = (const float*)d_in[0];
    const unsigned char* mask = (const unsigned char*)d_in[1];
    const float* w1  = (const float*)d_in[2];
    const float* b1  = (const float*)d_in[3];
    const float* w2  = (const float*)d_in[4];
    const float* b2  = (const float*)d_in[5];
    const float* inw = (const float*)d_in[6];
    const float* cw  = (const float*)d_in[7];
    const float* cb  = (const float*)d_in[8];
    const float* xpw = (const float*)d_in[9];
    const float* dtw = (const float*)d_in[10];
    const float* dtb = (const float*)d_in[11];
    const float* alg = (const float*)d_in[12];
    const float* dsk = (const float*)d_in[13];
    const float* ow  = (const float*)d_in[14];
    const float* bnw = (const float*)d_in[15];
    const float* nfw = (const float*)d_in[16];
    float* out = (float*)d_out;

    mamba_fused<<<NBLK, NTHR>>>(mha, mask, w1, b1, w2, b2, inw, cw, cb,
                                xpw, dtw, dtb, alg, dsk, ow, bnw, nfw, out);
}